// round 1
// baseline (speedup 1.0000x reference)
#include <cuda_runtime.h>
#include <math.h>

#define DD 128
#define SS 4096
#define BB 4

// Scratch for Q/K/V projections (no cudaMalloc allowed).
__device__ float g_Q[BB * SS * DD];
__device__ float g_K[BB * SS * DD];
__device__ float g_V[BB * SS * DD];

// ---------------- QKV projection: out = x @ W for 3 weights ----------------
#define GROWS 128
#define GTH 256

struct GemmSmem {
    float x[GROWS][DD + 4];   // stride 132 floats (16B-aligned rows)
    float w[DD][DD + 4];
};

__global__ __launch_bounds__(GTH) void qkv_kernel(const float* __restrict__ xg,
                                                  const float* __restrict__ wq,
                                                  const float* __restrict__ wk,
                                                  const float* __restrict__ wv) {
    extern __shared__ char raw[];
    GemmSmem& sm = *reinterpret_cast<GemmSmem*>(raw);
    const float* W;
    float* outp;
    if (blockIdx.y == 0)      { W = wq; outp = g_Q; }
    else if (blockIdx.y == 1) { W = wk; outp = g_K; }
    else                      { W = wv; outp = g_V; }

    const int t = threadIdx.x;
    const int rowbase = blockIdx.x * GROWS;

    // Load x tile (128x128) and W (128x128), coalesced float4.
    #pragma unroll
    for (int it = 0; it < 16; it++) {
        int lin = t + it * GTH;          // 0..4095
        int r = lin >> 5;
        int c4 = (lin & 31) << 2;
        *reinterpret_cast<float4*>(&sm.x[r][c4]) =
            *reinterpret_cast<const float4*>(xg + (rowbase + r) * DD + c4);
        *reinterpret_cast<float4*>(&sm.w[r][c4]) =
            *reinterpret_cast<const float4*>(W + r * DD + c4);
    }
    __syncthreads();

    const int tx = t & 7;     // 8 column groups: cols tx*4 + 32*j
    const int ty = t >> 3;    // 32 row groups: rows ty + 32*i

    float acc[4][16];
    #pragma unroll
    for (int i = 0; i < 4; i++)
        #pragma unroll
        for (int j = 0; j < 16; j++) acc[i][j] = 0.f;

    for (int k = 0; k < DD; k++) {
        float xv[4];
        #pragma unroll
        for (int i = 0; i < 4; i++) xv[i] = sm.x[ty + 32 * i][k];
        float4 wv[4];
        #pragma unroll
        for (int j = 0; j < 4; j++)
            wv[j] = *reinterpret_cast<const float4*>(&sm.w[k][tx * 4 + 32 * j]);
        #pragma unroll
        for (int i = 0; i < 4; i++) {
            #pragma unroll
            for (int j = 0; j < 4; j++) {
                acc[i][4 * j + 0] += xv[i] * wv[j].x;
                acc[i][4 * j + 1] += xv[i] * wv[j].y;
                acc[i][4 * j + 2] += xv[i] * wv[j].z;
                acc[i][4 * j + 3] += xv[i] * wv[j].w;
            }
        }
    }

    #pragma unroll
    for (int i = 0; i < 4; i++) {
        int r = rowbase + ty + 32 * i;
        #pragma unroll
        for (int j = 0; j < 4; j++) {
            float4 v = make_float4(acc[i][4 * j + 0], acc[i][4 * j + 1],
                                   acc[i][4 * j + 2], acc[i][4 * j + 3]);
            *reinterpret_cast<float4*>(outp + r * DD + tx * 4 + 32 * j) = v;
        }
    }
}

// ---------------- Flash attention (online softmax) ----------------
#define BQ 64
#define BK 64
#define FTH 256
#define PADD (DD + 4)    // 132 floats/row
#define SPAD 68

struct FlashSmem {
    float Q[BQ][PADD];
    float K[BK][PADD];
    float V[BK][PADD];   // column-XOR-swizzled in float4 units
    float P[BQ][SPAD];
    float m[BQ];
    float l[BQ];
    float alpha[BQ];
};

__global__ __launch_bounds__(FTH) void flash_kernel(float* __restrict__ outp) {
    extern __shared__ char raw[];
    FlashSmem& sm = *reinterpret_cast<FlashSmem*>(raw);
    const int t = threadIdx.x;
    const int b = blockIdx.x >> 6;       // S/BQ = 64 q-tiles per batch
    const int qt = blockIdx.x & 63;
    const int qbase = b * SS + qt * BQ;
    const float scale = 0.08838834764831845f;  // 1/sqrt(128)

    // Load + pre-scale Q tile.
    #pragma unroll
    for (int it = 0; it < 8; it++) {
        int lin = t + it * FTH;
        int r = lin >> 5;
        int c4 = (lin & 31) << 2;
        float4 v = *reinterpret_cast<const float4*>(g_Q + (qbase + r) * DD + c4);
        v.x *= scale; v.y *= scale; v.z *= scale; v.w *= scale;
        *reinterpret_cast<float4*>(&sm.Q[r][c4]) = v;
    }
    if (t < BQ) { sm.m[t] = -INFINITY; sm.l[t] = 0.f; }

    float o[32];
    #pragma unroll
    for (int j = 0; j < 32; j++) o[j] = 0.f;

    const int ty = t >> 4;            // 0..15: q rows ty + 16*i
    const int tx = t & 15;            // 0..15: k rows tx + 16*j
    const int qown = t >> 2;          // 0..63: PV owner row
    const int dg4 = (t & 3) << 3;     // d chunk base in float4 units (0,8,16,24)
    __syncthreads();

    for (int kt = 0; kt < SS / BK; kt++) {
        const int kbase = b * SS + kt * BK;
        // Load K (plain) and V (XOR-swizzled columns).
        #pragma unroll
        for (int it = 0; it < 8; it++) {
            int lin = t + it * FTH;
            int r = lin >> 5;
            int c4i = lin & 31;
            int c4 = c4i << 2;
            *reinterpret_cast<float4*>(&sm.K[r][c4]) =
                *reinterpret_cast<const float4*>(g_K + (kbase + r) * DD + c4);
            int sw = (c4i ^ ((c4i >> 3) & 3)) << 2;
            *reinterpret_cast<float4*>(&sm.V[r][sw]) =
                *reinterpret_cast<const float4*>(g_V + (kbase + r) * DD + c4);
        }
        __syncthreads();

        // Scores: 4x4 register tile per thread.
        float acc[4][4];
        #pragma unroll
        for (int i = 0; i < 4; i++)
            #pragma unroll
            for (int j = 0; j < 4; j++) acc[i][j] = 0.f;

        for (int d = 0; d < DD; d += 4) {
            float4 qv[4], kv[4];
            #pragma unroll
            for (int i = 0; i < 4; i++)
                qv[i] = *reinterpret_cast<const float4*>(&sm.Q[ty + 16 * i][d]);
            #pragma unroll
            for (int j = 0; j < 4; j++)
                kv[j] = *reinterpret_cast<const float4*>(&sm.K[tx + 16 * j][d]);
            #pragma unroll
            for (int i = 0; i < 4; i++) {
                #pragma unroll
                for (int j = 0; j < 4; j++) {
                    acc[i][j] += qv[i].x * kv[j].x;
                    acc[i][j] += qv[i].y * kv[j].y;
                    acc[i][j] += qv[i].z * kv[j].z;
                    acc[i][j] += qv[i].w * kv[j].w;
                }
            }
        }
        #pragma unroll
        for (int i = 0; i < 4; i++)
            #pragma unroll
            for (int j = 0; j < 4; j++)
                sm.P[ty + 16 * i][tx + 16 * j] = acc[i][j];
        __syncthreads();

        // Online softmax: one thread per q row.
        if (t < BQ) {
            float mold = sm.m[t];
            float mx = mold;
            #pragma unroll
            for (int j = 0; j < BK; j++) mx = fmaxf(mx, sm.P[t][j]);
            float a = __expf(mold - mx);   // exp(-inf)=0 on first tile
            float ssum = 0.f;
            #pragma unroll
            for (int j = 0; j < BK; j++) {
                float p = __expf(sm.P[t][j] - mx);
                sm.P[t][j] = p;
                ssum += p;
            }
            sm.m[t] = mx;
            sm.l[t] = sm.l[t] * a + ssum;
            sm.alpha[t] = a;
        }
        __syncthreads();

        // PV accumulation: thread owns (qown, 32 dims starting at dg4*4).
        float a = sm.alpha[qown];
        #pragma unroll
        for (int j = 0; j < 32; j++) o[j] *= a;
        for (int k = 0; k < BK; k++) {
            float p = sm.P[qown][k];
            #pragma unroll
            for (int jj = 0; jj < 8; jj++) {
                int c4i = dg4 + jj;
                int sw = (c4i ^ ((c4i >> 3) & 3)) << 2;
                float4 v = *reinterpret_cast<const float4*>(&sm.V[k][sw]);
                o[jj * 4 + 0] += p * v.x;
                o[jj * 4 + 1] += p * v.y;
                o[jj * 4 + 2] += p * v.z;
                o[jj * 4 + 3] += p * v.w;
            }
        }
        __syncthreads();   // protect K/V/P before next tile's loads
    }

    const float inv = 1.f / sm.l[qown];
    const int orow = qbase + qown;
    #pragma unroll
    for (int jj = 0; jj < 8; jj++) {
        float4 v = make_float4(o[jj * 4 + 0] * inv, o[jj * 4 + 1] * inv,
                               o[jj * 4 + 2] * inv, o[jj * 4 + 3] * inv);
        *reinterpret_cast<float4*>(outp + orow * DD + (dg4 << 2) + jj * 4) = v;
    }
}

extern "C" void kernel_launch(void* const* d_in, const int* in_sizes, int n_in,
                              void* d_out, int out_size) {
    const float* x  = (const float*)d_in[0];
    // d_in[1] = token_attention_masks (int64) — unused by the reference math.
    const float* wq = (const float*)d_in[2];
    const float* wk = (const float*)d_in[3];
    const float* wv = (const float*)d_in[4];
    float* out = (float*)d_out;

    cudaFuncSetAttribute(qkv_kernel, cudaFuncAttributeMaxDynamicSharedMemorySize,
                         (int)sizeof(GemmSmem));
    cudaFuncSetAttribute(flash_kernel, cudaFuncAttributeMaxDynamicSharedMemorySize,
                         (int)sizeof(FlashSmem));

    dim3 g1((BB * SS) / GROWS, 3);
    qkv_kernel<<<g1, GTH, sizeof(GemmSmem)>>>(x, wq, wk, wv);
    flash_kernel<<<BB * (SS / BQ), FTH, sizeof(FlashSmem)>>>(out);
}